// round 13
// baseline (speedup 1.0000x reference)
#include <cuda_runtime.h>
#include <cuda_bf16.h>
#include <cstdint>

#define CH     512
#define HW     4096
#define SCALE  (1.0e6f / 33554432.0f)
#define NGEMM  144    // 36 upper-tri 64x64 tiles x splitK 4
#define NCTA   720    // must be <= 5 CTAs/SM * 148 SMs = 740 (grid barrier!)
#define NUNITS 1024   // loss units: (row r) x (half of j)
#define PF4    4194304 // prefetch 4M float4 = 64MB of target

__device__ __align__(16) __nv_bfloat16 g_feats[CH * HW];  // 4 MB bf16 feats
__device__ __align__(16) float g_G[CH * CH];              // gram (scaled 1/2^20)
__device__ unsigned int g_wbase;  // ticket base snapshot (written by CTA0 each launch)
__device__ unsigned int g_work;   // ticket ctr (monotonic, never reset)
__device__ unsigned int g_gdone;  // gemm-done ctr (monotonic, +NGEMM per launch)
__device__ unsigned int g_barA;   // monotonic, +NCTA per launch
__device__ unsigned int g_barB;   // monotonic, +NCTA per launch

// ---------------------------------------------------------------------------
__device__ __forceinline__ uint32_t smem_u32(const void* p) {
    return static_cast<uint32_t>(__cvta_generic_to_shared(p));
}
__device__ __forceinline__ void cp_async16(uint32_t dst, const void* src) {
    asm volatile("cp.async.cg.shared.global [%0], [%1], 16;\n" :: "r"(dst), "l"(src));
}
template <int N>
__device__ __forceinline__ void cp_wait() {
    asm volatile("cp.async.wait_group %0;\n" :: "n"(N) : "memory");
}
__device__ __forceinline__ void cp_commit() {
    asm volatile("cp.async.commit_group;\n" ::: "memory");
}
__device__ __forceinline__ void ldm_x4(uint32_t* d, uint32_t addr) {
    asm volatile("ldmatrix.sync.aligned.m8n8.x4.shared.b16 {%0,%1,%2,%3}, [%4];"
                 : "=r"(d[0]), "=r"(d[1]), "=r"(d[2]), "=r"(d[3]) : "r"(addr));
}
__device__ __forceinline__ void mma_bf16(float* c, const uint32_t* a, uint32_t b0, uint32_t b1) {
    asm volatile("mma.sync.aligned.m16n8k16.row.col.f32.bf16.bf16.f32 "
                 "{%0,%1,%2,%3},{%4,%5,%6,%7},{%8,%9},{%0,%1,%2,%3};"
                 : "+f"(c[0]), "+f"(c[1]), "+f"(c[2]), "+f"(c[3])
                 : "r"(a[0]), "r"(a[1]), "r"(a[2]), "r"(a[3]), "r"(b0), "r"(b1));
}
__device__ __forceinline__ void spin_to(unsigned int* ctr, unsigned tgt) {
    unsigned cur;
    do {
        __nanosleep(64);
        asm volatile("ld.acquire.gpu.u32 %0, [%1];" : "=r"(cur) : "l"(ctr));
    } while (cur < tgt);
}
__device__ __forceinline__ unsigned ld_acq(unsigned int* p) {
    unsigned v;
    asm volatile("ld.acquire.gpu.u32 %0, [%1];" : "=r"(v) : "l"(p));
    return v;
}
// XOR-swizzled byte offset within a 64-row x 128B tile
__device__ __forceinline__ uint32_t swz(int row, int c16) {
    return (uint32_t)((row * 128 + c16 * 16) ^ ((row & 7) << 4));
}

// smem 32832B: GEMM ring 2 slots x 16KB (A @0, B @8192 per slot)
//              loss: sG[512] @0 (2KB)
//              tk/stop @32768 (int), red[8] @32772
__global__ void __launch_bounds__(256, 5) k_all(const float* __restrict__ x,
                                                const float* __restrict__ target,
                                                float* __restrict__ out) {
    __shared__ __align__(16) char sm[32832];
    int*   tkp = reinterpret_cast<int*>(sm + 32768);
    float* red = reinterpret_cast<float*>(sm + 32772);
    const int t = threadIdx.x;
    const int w = t >> 5, l = t & 31;
    const int bid = blockIdx.x;

    // ============ Phase 1: convert x -> bf16 (all CTAs), zero G ============
    const int gi = bid * 256 + t;                 // 0..184319
    for (int idx = gi; idx < 524288; idx += NCTA * 256) {
        float4 v = reinterpret_cast<const float4*>(x)[idx];
        __nv_bfloat162 p0, p1;
        p0.x = __float2bfloat16(v.x); p0.y = __float2bfloat16(v.y);
        p1.x = __float2bfloat16(v.z); p1.y = __float2bfloat16(v.w);
        uint2 pk;
        pk.x = *reinterpret_cast<uint32_t*>(&p0);
        pk.y = *reinterpret_cast<uint32_t*>(&p1);
        reinterpret_cast<uint2*>(g_feats)[idx] = pk;
    }
    if (gi < 65536)
        reinterpret_cast<float4*>(g_G)[gi] = make_float4(0.f, 0.f, 0.f, 0.f);
    if (gi == 0) {
        out[0] = 0.0f;
        g_wbase = g_work;           // snapshot ticket base for this launch
    }

    __threadfence();
    __syncthreads();
    unsigned gd_tgt = 0;
    if (t == 0) {
        gd_tgt = ld_acq(&g_gdone) + NGEMM;        // capture BEFORE barA arrival
        unsigned old = atomicAdd(&g_barA, 1u);
        if (bid < NGEMM) {
            unsigned tgtA = old - (old % NCTA) + NCTA;
            spin_to(&g_barA, tgtA);               // GEMM waits for feats + zeroed G
        }
    }

    if (bid < NGEMM) {
        // ====== GEMM: 64x64 upper-tri tiles, splitK 4, XOR-swizzled 2-stage ======
        __syncthreads();
        const int tile = bid % 36;
        const int kz   = (bid / 36) * 1024;
        int rem = tile, bi = 0;
        while (rem >= 8 - bi) { rem -= 8 - bi; bi++; }
        const int bj = bi + rem;
        const int m0 = bi * 64, n0 = bj * 64;

        const int wm = (w & 1) * 32;     // 0,32
        const int wn = (w >> 1) * 16;    // 0..48

        float acc[2][2][4];
        #pragma unroll
        for (int a = 0; a < 2; a++)
          #pragma unroll
          for (int h = 0; h < 2; h++)
            #pragma unroll
            for (int q = 0; q < 4; q++) acc[a][h][q] = 0.f;

        const int lrow = l & 15;
        const int lkh2 = (l >> 4) * 16;  // byte offset of k-half
        const int srow = t >> 2;         // 0..63 staging row
        const int sch  = t & 3;          // chunk 0..3 (+4 for second)
        const uint32_t smb = smem_u32(sm);

        #define GLOAD(KS, SL) do {                                           \
            const int kb_ = kz + (KS) * 64;                                  \
            _Pragma("unroll")                                                \
            for (int p_ = 0; p_ < 2; p_++) {                                 \
                const int c_ = sch + p_ * 4;                                 \
                cp_async16(smb + (SL) * 16384 + swz(srow, c_),               \
                           &g_feats[(m0 + srow) * HW + kb_ + c_ * 8]);       \
                cp_async16(smb + (SL) * 16384 + 8192 + swz(srow, c_),        \
                           &g_feats[(n0 + srow) * HW + kb_ + c_ * 8]);       \
            }                                                                \
            cp_commit();                                                     \
        } while (0)

        GLOAD(0, 0);
        for (int ks = 0; ks < 16; ks++) {
            const int buf = ks & 1;
            if (ks < 15) {
                GLOAD(ks + 1, buf ^ 1);
                cp_wait<1>();
            } else {
                cp_wait<0>();
            }
            __syncthreads();

            #pragma unroll
            for (int k16 = 0; k16 < 4; k16++) {
                uint32_t afr[2][4], bfr[4];
                #pragma unroll
                for (int mt = 0; mt < 2; mt++) {
                    const int ra = wm + mt * 16 + lrow;
                    ldm_x4(afr[mt], smb + buf * 16384 + swz(ra, 0)
                                    + (uint32_t)(k16 * 32 + lkh2)
                                    - (uint32_t)0 * 0
                                    // swz applied to full byte offset:
                                    );
                }
                // NOTE: swizzle must include the column; recompute properly:
                #pragma unroll
                for (int mt = 0; mt < 2; mt++) {
                    const int ra = wm + mt * 16 + lrow;
                    const uint32_t off = (uint32_t)((ra * 128 + k16 * 32 + lkh2)
                                                    ^ ((ra & 7) << 4));
                    ldm_x4(afr[mt], smb + buf * 16384 + off);
                }
                {
                    const int rb = wn + lrow;
                    const uint32_t off = (uint32_t)((rb * 128 + k16 * 32 + lkh2)
                                                    ^ ((rb & 7) << 4));
                    ldm_x4(bfr, smb + buf * 16384 + 8192 + off);
                }
                #pragma unroll
                for (int mt = 0; mt < 2; mt++) {
                    mma_bf16(acc[mt][0], afr[mt], bfr[0], bfr[2]);
                    mma_bf16(acc[mt][1], afr[mt], bfr[1], bfr[3]);
                }
            }
            __syncthreads();
        }
        #undef GLOAD

        const float s = 1.0f / 1048576.0f;
        const int g2 = l >> 2, cc = (l & 3) * 2;
        const bool mirror = (bi != bj);
        #pragma unroll
        for (int mt = 0; mt < 2; mt++)
          #pragma unroll
          for (int h = 0; h < 2; h++) {
            const int row = m0 + wm + mt * 16 + g2;
            const int col = n0 + wn + h * 8 + cc;
            const float v0 = acc[mt][h][0] * s;
            const float v1 = acc[mt][h][1] * s;
            const float v2 = acc[mt][h][2] * s;
            const float v3 = acc[mt][h][3] * s;
            atomicAdd(&g_G[row * CH + col],           v0);
            atomicAdd(&g_G[row * CH + col + 1],       v1);
            atomicAdd(&g_G[(row + 8) * CH + col],     v2);
            atomicAdd(&g_G[(row + 8) * CH + col + 1], v3);
            if (mirror) {
                atomicAdd(&g_G[col * CH + row],           v0);
                atomicAdd(&g_G[(col + 1) * CH + row],     v1);
                atomicAdd(&g_G[col * CH + row + 8],       v2);
                atomicAdd(&g_G[(col + 1) * CH + row + 8], v3);
            }
          }

        __threadfence();
        __syncthreads();
        if (t == 0) atomicAdd(&g_gdone, 1u);      // signal prefetchers
    } else {
        // ====== Prefetch target into L2 while GEMM runs ======
        if (t == 0) *tkp = 0;
        __syncthreads();
        const int c = bid - NGEMM;                // 0..575
        const float4* tg4 = reinterpret_cast<const float4*>(target);
        for (int b4 = c * 2048; b4 < PF4; b4 += (NCTA - NGEMM) * 2048) {
            if (*tkp) break;
            float s0 = 0.f;
            #pragma unroll
            for (int u = 0; u < 8; u++) {
                float4 v = __ldg(&tg4[b4 + u * 256 + t]);
                s0 += v.x + v.y + v.z + v.w;
            }
            asm volatile("" :: "f"(s0));          // keep the loads
            if (t == 0 && ld_acq(&g_gdone) >= gd_tgt) *tkp = 1;
            __syncthreads();
        }
    }

    // ============ full barrier: G complete, then direct loss ============
    __threadfence();
    __syncthreads();
    if (t == 0) {
        unsigned old = atomicAdd(&g_barB, 1u);
        unsigned tgt = old - (old % NCTA) + NCTA;
        spin_to(&g_barB, tgt);
    }
    __syncthreads();

    float* sG = reinterpret_cast<float*>(sm);
    const unsigned wb = ld_acq(&g_wbase);
    float accum = 0.f;

    while (true) {
        if (t == 0) *tkp = (int)(atomicAdd(&g_work, 1u) - wb);
        __syncthreads();
        const int tk = *tkp;
        __syncthreads();                 // also guards sG overwrite vs prior reads
        if (tk >= NUNITS) break;

        const int r  = tk >> 1;
        const int j0 = (tk & 1) << 7;
        sG[t]       = g_G[(r << 9) + t];
        sG[t + 256] = g_G[(r << 9) + 256 + t];
        __syncthreads();

        #pragma unroll 1
        for (int jb = j0; jb < j0 + 128; jb += 8) {
            float tv[8];
            #pragma unroll
            for (int u = 0; u < 8; u++) {
                const int j = jb + u;
                const int i = (r - j) & 511;
                tv[u] = __ldg(&target[(i << 16) + (j << 8) + t]);
            }
            #pragma unroll
            for (int u = 0; u < 8; u++) {
                const int i = (r - (jb + u)) & 511;
                const float d = sG[(i + t) & 511] - tv[u];
                accum = fmaf(d, d, accum);
            }
        }
    }

    // final reduce + single atomic per CTA
    #pragma unroll
    for (int o = 16; o > 0; o >>= 1)
        accum += __shfl_xor_sync(0xFFFFFFFFu, accum, o);
    if (l == 0) red[w] = accum;
    __syncthreads();
    if (t == 0) {
        float z = 0.f;
        #pragma unroll
        for (int ww = 0; ww < 8; ww++) z += red[ww];
        atomicAdd(out, z * SCALE);
    }
}

// ---------------------------------------------------------------------------
extern "C" void kernel_launch(void* const* d_in, const int* in_sizes, int n_in,
                              void* d_out, int out_size) {
    const float* x      = (const float*)d_in[0];   // (1,512,64,64) fp32
    const float* target = (const float*)d_in[1];   // (512,256,256) fp32
    float* out = (float*)d_out;

    k_all<<<NCTA, 256>>>(x, target, out);
}

// round 14
// speedup vs baseline: 1.0128x; 1.0128x over previous
#include <cuda_runtime.h>
#include <cuda_bf16.h>
#include <cstdint>

#define CH     512
#define HW     4096
#define SCALE  (1.0e6f / 33554432.0f)
#define NGEMM  144    // 36 upper-tri 64x64 tiles x splitK 4
#define NCTA   720    // <= 5 CTAs/SM * 148 SMs = 740 (grid barrier safety)
#define NPF    (NCTA - NGEMM)
#define NUNITS 2048   // loss units: (row r: 0..511) x (j-quarter: 64 j's)

__device__ __align__(16) __nv_bfloat16 g_feats[CH * HW];  // 4 MB bf16 feats
__device__ __align__(16) float g_G[CH * CH];              // gram (scaled 1/2^20)
__device__ unsigned int g_wbase;  // ticket base snapshot (rewritten each launch)
__device__ unsigned int g_work;   // ticket ctr (monotonic, never reset)
__device__ unsigned int g_gdone;  // gemm-done ctr (monotonic, +NGEMM per launch)
__device__ unsigned int g_barA;   // monotonic, +NCTA per launch
__device__ unsigned int g_barB;   // monotonic, +NCTA per launch

// ---------------------------------------------------------------------------
__device__ __forceinline__ uint32_t smem_u32(const void* p) {
    return static_cast<uint32_t>(__cvta_generic_to_shared(p));
}
__device__ __forceinline__ void cp_async16(uint32_t dst, const void* src) {
    asm volatile("cp.async.cg.shared.global [%0], [%1], 16;\n" :: "r"(dst), "l"(src));
}
template <int N>
__device__ __forceinline__ void cp_wait() {
    asm volatile("cp.async.wait_group %0;\n" :: "n"(N) : "memory");
}
__device__ __forceinline__ void cp_commit() {
    asm volatile("cp.async.commit_group;\n" ::: "memory");
}
__device__ __forceinline__ void ldm_x4(uint32_t* d, uint32_t addr) {
    asm volatile("ldmatrix.sync.aligned.m8n8.x4.shared.b16 {%0,%1,%2,%3}, [%4];"
                 : "=r"(d[0]), "=r"(d[1]), "=r"(d[2]), "=r"(d[3]) : "r"(addr));
}
__device__ __forceinline__ void mma_bf16(float* c, const uint32_t* a, uint32_t b0, uint32_t b1) {
    asm volatile("mma.sync.aligned.m16n8k16.row.col.f32.bf16.bf16.f32 "
                 "{%0,%1,%2,%3},{%4,%5,%6,%7},{%8,%9},{%0,%1,%2,%3};"
                 : "+f"(c[0]), "+f"(c[1]), "+f"(c[2]), "+f"(c[3])
                 : "r"(a[0]), "r"(a[1]), "r"(a[2]), "r"(a[3]), "r"(b0), "r"(b1));
}
__device__ __forceinline__ void spin_to(unsigned int* ctr, unsigned tgt) {
    unsigned cur;
    do {
        __nanosleep(64);
        asm volatile("ld.acquire.gpu.u32 %0, [%1];" : "=r"(cur) : "l"(ctr));
    } while (cur < tgt);
}
__device__ __forceinline__ unsigned ld_acq(unsigned int* p) {
    unsigned v;
    asm volatile("ld.acquire.gpu.u32 %0, [%1];" : "=r"(v) : "l"(p));
    return v;
}

// smem 32832B: GEMM ring 2 slots x 16KB (A @0, B @8192 within each slot)
//              loss: sG[512] @0 (2KB) ; tkp @32768, red[8] @32772
__global__ void __launch_bounds__(256, 5) k_all(const float* __restrict__ x,
                                                const float* __restrict__ target,
                                                float* __restrict__ out) {
    __shared__ __align__(16) char sm[32832];
    int*   tkp = reinterpret_cast<int*>(sm + 32768);
    float* red = reinterpret_cast<float*>(sm + 32772);
    const int t = threadIdx.x;
    const int w = t >> 5, l = t & 31;
    const int bid = blockIdx.x;

    // ============ Phase 1: convert x -> bf16 (all CTAs), zero G ============
    const int gi = bid * 256 + t;
    for (int idx = gi; idx < 524288; idx += NCTA * 256) {
        float4 v = reinterpret_cast<const float4*>(x)[idx];
        __nv_bfloat162 p0, p1;
        p0.x = __float2bfloat16(v.x); p0.y = __float2bfloat16(v.y);
        p1.x = __float2bfloat16(v.z); p1.y = __float2bfloat16(v.w);
        uint2 pk;
        pk.x = *reinterpret_cast<uint32_t*>(&p0);
        pk.y = *reinterpret_cast<uint32_t*>(&p1);
        reinterpret_cast<uint2*>(g_feats)[idx] = pk;
    }
    if (gi < 65536)
        reinterpret_cast<float4*>(g_G)[gi] = make_float4(0.f, 0.f, 0.f, 0.f);
    if (gi == 0) {
        out[0] = 0.0f;
        g_wbase = g_work;           // snapshot ticket base for this launch
    }

    // capture gemm-done base BEFORE anyone can increment it (pre-barA)
    const unsigned gd_tgt = ld_acq(&g_gdone) + NGEMM;

    __threadfence();
    __syncthreads();
    if (t == 0) {
        unsigned old = atomicAdd(&g_barA, 1u);
        if (bid < NGEMM) {
            unsigned tgtA = old - (old % NCTA) + NCTA;
            spin_to(&g_barA, tgtA);               // GEMM waits for feats + zero G
        }
    }

    if (bid < NGEMM) {
        // ====== GEMM: 64x64 upper-tri tiles, splitK 4, 2-stage XOR swizzle ======
        __syncthreads();
        const int tile = bid % 36;
        const int kz   = (bid / 36) * 1024;
        int rem = tile, bi = 0;
        while (rem >= 8 - bi) { rem -= 8 - bi; bi++; }
        const int bj = bi + rem;
        const int m0 = bi * 64, n0 = bj * 64;

        const int wm = (w & 1) * 32;     // 0,32
        const int wn = (w >> 1) * 16;    // 0..48

        float acc[2][2][4];
        #pragma unroll
        for (int a = 0; a < 2; a++)
          #pragma unroll
          for (int h = 0; h < 2; h++)
            #pragma unroll
            for (int q = 0; q < 4; q++) acc[a][h][q] = 0.f;

        const int lrow = l & 15;
        const int lkh2 = (l >> 4) * 16;  // byte offset of k-half
        const int srow = t >> 2;         // 0..63 staging row
        const int sch  = t & 3;          // chunk 0..3 (+4 for second)
        const uint32_t smb = smem_u32(sm);

        #define GLOAD(KS, SL) do {                                           \
            const int kb_ = kz + (KS) * 64;                                  \
            _Pragma("unroll")                                                \
            for (int p_ = 0; p_ < 2; p_++) {                                 \
                const int c_ = sch + p_ * 4;                                 \
                const uint32_t so_ = (uint32_t)((srow * 128 + c_ * 16)       \
                                                ^ ((srow & 7) << 4));        \
                cp_async16(smb + (SL) * 16384 + so_,                         \
                           &g_feats[(m0 + srow) * HW + kb_ + c_ * 8]);       \
                cp_async16(smb + (SL) * 16384 + 8192 + so_,                  \
                           &g_feats[(n0 + srow) * HW + kb_ + c_ * 8]);       \
            }                                                                \
            cp_commit();                                                     \
        } while (0)

        GLOAD(0, 0);
        for (int ks = 0; ks < 16; ks++) {
            const int buf = ks & 1;
            if (ks < 15) {
                GLOAD(ks + 1, buf ^ 1);
                cp_wait<1>();
            } else {
                cp_wait<0>();
            }
            __syncthreads();

            #pragma unroll
            for (int k16 = 0; k16 < 4; k16++) {
                uint32_t afr[2][4], bfr[4];
                #pragma unroll
                for (int mt = 0; mt < 2; mt++) {
                    const int ra = wm + mt * 16 + lrow;
                    const uint32_t off = (uint32_t)((ra * 128 + k16 * 32 + lkh2)
                                                    ^ ((ra & 7) << 4));
                    ldm_x4(afr[mt], smb + buf * 16384 + off);
                }
                {
                    const int rb = wn + lrow;
                    const uint32_t off = (uint32_t)((rb * 128 + k16 * 32 + lkh2)
                                                    ^ ((rb & 7) << 4));
                    ldm_x4(bfr, smb + buf * 16384 + 8192 + off);
                }
                #pragma unroll
                for (int mt = 0; mt < 2; mt++) {
                    mma_bf16(acc[mt][0], afr[mt], bfr[0], bfr[2]);
                    mma_bf16(acc[mt][1], afr[mt], bfr[1], bfr[3]);
                }
            }
            __syncthreads();
        }
        #undef GLOAD

        const float s = 1.0f / 1048576.0f;
        const int g2 = l >> 2, cc = (l & 3) * 2;
        const bool mirror = (bi != bj);
        #pragma unroll
        for (int mt = 0; mt < 2; mt++)
          #pragma unroll
          for (int h = 0; h < 2; h++) {
            const int row = m0 + wm + mt * 16 + g2;
            const int col = n0 + wn + h * 8 + cc;
            const float v0 = acc[mt][h][0] * s;
            const float v1 = acc[mt][h][1] * s;
            const float v2 = acc[mt][h][2] * s;
            const float v3 = acc[mt][h][3] * s;
            atomicAdd(&g_G[row * CH + col],           v0);
            atomicAdd(&g_G[row * CH + col + 1],       v1);
            atomicAdd(&g_G[(row + 8) * CH + col],     v2);
            atomicAdd(&g_G[(row + 8) * CH + col + 1], v3);
            if (mirror) {
                atomicAdd(&g_G[col * CH + row],           v0);
                atomicAdd(&g_G[(col + 1) * CH + row],     v1);
                atomicAdd(&g_G[col * CH + row + 8],       v2);
                atomicAdd(&g_G[(col + 1) * CH + row + 8], v3);
            }
          }

        __threadfence();
        __syncthreads();
        if (t == 0) atomicAdd(&g_gdone, 1u);      // release prefetchers
    } else {
        // ====== Lean L2 prefetch of target while GEMM runs (no CTA syncs) ======
        const float4* tg4 = reinterpret_cast<const float4*>(target);
        float dummy = 0.f;
        int idx = (bid - NGEMM) * 256 + t;        // stride NPF*256 per load
        #pragma unroll 1
        for (int it = 0; it < 16; it++) {
            #pragma unroll
            for (int u = 0; u < 4; u++) {
                if (idx < 8388608) {
                    float4 v = __ldg(&tg4[idx]);
                    dummy += v.x + v.y + v.z + v.w;
                }
                idx += NPF * 256;
            }
            if (((it & 1) == 1)) {
                unsigned g = 0;
                if (l == 0) g = ld_acq(&g_gdone);
                g = __shfl_sync(0xFFFFFFFFu, g, 0);
                if (g >= gd_tgt) break;
            }
        }
        asm volatile("" :: "f"(dummy));           // keep the loads
    }

    // ============ full barrier: G complete ============
    __threadfence();
    __syncthreads();
    if (t == 0) {
        unsigned old = atomicAdd(&g_barB, 1u);
        unsigned tgt = old - (old % NCTA) + NCTA;
        spin_to(&g_barB, tgt);
    }
    __syncthreads();

    // ============ Direct loss: work-steal (r, j-quarter) units ============
    float* sG = reinterpret_cast<float*>(sm);
    const unsigned wb = ld_acq(&g_wbase);
    const float* tgt_t = target + t;
    float accum = 0.f;

    while (true) {
        if (t == 0) *tkp = (int)(atomicAdd(&g_work, 1u) - wb);
        __syncthreads();
        const int tk = *tkp;
        __syncthreads();
        if (tk >= NUNITS) break;

        const int r  = tk >> 2;
        const int j0 = (tk & 3) << 6;             // 64 j's
        sG[t]       = g_G[(r << 9) + t];
        sG[t + 256] = g_G[(r << 9) + 256 + t];
        __syncthreads();

        #pragma unroll 1
        for (int jb = j0; jb < j0 + 64; jb += 8) {
            float tv[8];
            #pragma unroll
            for (int u = 0; u < 8; u++) {
                const int j = jb + u;
                const int i = (r - j) & 511;
                tv[u] = __ldg(tgt_t + ((i << 16) + (j << 8)));
            }
            #pragma unroll
            for (int u = 0; u < 8; u++) {
                const int i = (r - (jb + u)) & 511;
                const float d = sG[(i + t) & 511] - tv[u];
                accum = fmaf(d, d, accum);
            }
        }
    }

    // final reduce + single atomic per CTA
    #pragma unroll
    for (int o = 16; o > 0; o >>= 1)
        accum += __shfl_xor_sync(0xFFFFFFFFu, accum, o);
    if (l == 0) red[w] = accum;
    __syncthreads();
    if (t == 0) {
        float z = 0.f;
        #pragma unroll
        for (int ww = 0; ww < 8; ww++) z += red[ww];
        atomicAdd(out, z * SCALE);
    }
}

// ---------------------------------------------------------------------------
extern "C" void kernel_launch(void* const* d_in, const int* in_sizes, int n_in,
                              void* d_out, int out_size) {
    const float* x      = (const float*)d_in[0];   // (1,512,64,64) fp32
    const float* target = (const float*)d_in[1];   // (512,256,256) fp32
    float* out = (float*)d_out;

    k_all<<<NCTA, 256>>>(x, target, out);
}

// round 15
// speedup vs baseline: 1.0888x; 1.0750x over previous
#include <cuda_runtime.h>
#include <cuda_bf16.h>
#include <cstdint>

#define CH     512
#define HW     4096
#define SCALE  (1.0e6f / 33554432.0f)
#define NGEMM  144    // 36 upper-tri 64x64 tiles x splitK 4
#define NCTA   720    // <= 5 CTAs/SM * 148 SMs = 740 (grid barrier safety)
#define NPF    (NCTA - NGEMM)
#define NUNITS 8192   // loss units: 16 consecutive target rows (16KB) each

__device__ __align__(16) __nv_bfloat16 g_feats[CH * HW];  // 4 MB bf16 feats
__device__ __align__(16) float g_G[CH * CH];              // gram (scaled 1/2^20)
__device__ unsigned int g_wbase;  // ticket base snapshot (rewritten each launch)
__device__ unsigned int g_work;   // ticket ctr (monotonic, never reset)
__device__ unsigned int g_gdone;  // gemm-done ctr (monotonic, +NGEMM per launch)
__device__ unsigned int g_barA;   // monotonic, +NCTA per launch
__device__ unsigned int g_barB;   // monotonic, +NCTA per launch

// ---------------------------------------------------------------------------
__device__ __forceinline__ uint32_t smem_u32(const void* p) {
    return static_cast<uint32_t>(__cvta_generic_to_shared(p));
}
__device__ __forceinline__ void cp_async16(uint32_t dst, const void* src) {
    asm volatile("cp.async.cg.shared.global [%0], [%1], 16;\n" :: "r"(dst), "l"(src));
}
template <int N>
__device__ __forceinline__ void cp_wait() {
    asm volatile("cp.async.wait_group %0;\n" :: "n"(N) : "memory");
}
__device__ __forceinline__ void cp_commit() {
    asm volatile("cp.async.commit_group;\n" ::: "memory");
}
__device__ __forceinline__ void ldm_x4(uint32_t* d, uint32_t addr) {
    asm volatile("ldmatrix.sync.aligned.m8n8.x4.shared.b16 {%0,%1,%2,%3}, [%4];"
                 : "=r"(d[0]), "=r"(d[1]), "=r"(d[2]), "=r"(d[3]) : "r"(addr));
}
__device__ __forceinline__ void mma_bf16(float* c, const uint32_t* a, uint32_t b0, uint32_t b1) {
    asm volatile("mma.sync.aligned.m16n8k16.row.col.f32.bf16.bf16.f32 "
                 "{%0,%1,%2,%3},{%4,%5,%6,%7},{%8,%9},{%0,%1,%2,%3};"
                 : "+f"(c[0]), "+f"(c[1]), "+f"(c[2]), "+f"(c[3])
                 : "r"(a[0]), "r"(a[1]), "r"(a[2]), "r"(a[3]), "r"(b0), "r"(b1));
}
__device__ __forceinline__ void spin_to(unsigned int* ctr, unsigned tgt) {
    unsigned cur;
    do {
        __nanosleep(64);
        asm volatile("ld.acquire.gpu.u32 %0, [%1];" : "=r"(cur) : "l"(ctr));
    } while (cur < tgt);
}
__device__ __forceinline__ unsigned ld_acq(unsigned int* p) {
    unsigned v;
    asm volatile("ld.acquire.gpu.u32 %0, [%1];" : "=r"(v) : "l"(p));
    return v;
}

// smem 32832B: GEMM ring 2 slots x 16KB (A @0, B @8192 within each slot)
//              tkp @32768, red[8] @32772
__global__ void __launch_bounds__(256, 5) k_all(const float* __restrict__ x,
                                                const float* __restrict__ target,
                                                float* __restrict__ out) {
    __shared__ __align__(16) char sm[32832];
    int*   tkp = reinterpret_cast<int*>(sm + 32768);
    float* red = reinterpret_cast<float*>(sm + 32772);
    const int t = threadIdx.x;
    const int w = t >> 5, l = t & 31;
    const int bid = blockIdx.x;

    // ============ Phase 1: convert x -> bf16 (all CTAs), zero G ============
    const int gi = bid * 256 + t;
    for (int idx = gi; idx < 524288; idx += NCTA * 256) {
        float4 v = reinterpret_cast<const float4*>(x)[idx];
        __nv_bfloat162 p0, p1;
        p0.x = __float2bfloat16(v.x); p0.y = __float2bfloat16(v.y);
        p1.x = __float2bfloat16(v.z); p1.y = __float2bfloat16(v.w);
        uint2 pk;
        pk.x = *reinterpret_cast<uint32_t*>(&p0);
        pk.y = *reinterpret_cast<uint32_t*>(&p1);
        reinterpret_cast<uint2*>(g_feats)[idx] = pk;
    }
    if (gi < 65536)
        reinterpret_cast<float4*>(g_G)[gi] = make_float4(0.f, 0.f, 0.f, 0.f);
    if (gi == 0) {
        out[0] = 0.0f;
        g_wbase = g_work;           // snapshot ticket base for this launch
    }

    // capture gemm-done base BEFORE anyone can pass barA and increment it
    const unsigned gd_tgt = ld_acq(&g_gdone) + NGEMM;

    __threadfence();
    __syncthreads();
    if (t == 0) {
        unsigned old = atomicAdd(&g_barA, 1u);
        if (bid < NGEMM) {
            unsigned tgtA = old - (old % NCTA) + NCTA;
            spin_to(&g_barA, tgtA);               // GEMM waits for feats + zero G
        }
    }

    if (bid < NGEMM) {
        // ====== GEMM: 64x64 upper-tri tiles, splitK 4, 2-stage XOR swizzle ======
        __syncthreads();
        const int tile = bid % 36;
        const int kz   = (bid / 36) * 1024;
        int rem = tile, bi = 0;
        while (rem >= 8 - bi) { rem -= 8 - bi; bi++; }
        const int bj = bi + rem;
        const int m0 = bi * 64, n0 = bj * 64;

        const int wm = (w & 1) * 32;     // 0,32
        const int wn = (w >> 1) * 16;    // 0..48

        float acc[2][2][4];
        #pragma unroll
        for (int a = 0; a < 2; a++)
          #pragma unroll
          for (int h = 0; h < 2; h++)
            #pragma unroll
            for (int q = 0; q < 4; q++) acc[a][h][q] = 0.f;

        const int lrow = l & 15;
        const int lkh2 = (l >> 4) * 16;  // byte offset of k-half
        const int srow = t >> 2;         // 0..63 staging row
        const int sch  = t & 3;          // chunk 0..3 (+4 for second)
        const uint32_t smb = smem_u32(sm);

        #define GLOAD(KS, SL) do {                                           \
            const int kb_ = kz + (KS) * 64;                                  \
            _Pragma("unroll")                                                \
            for (int p_ = 0; p_ < 2; p_++) {                                 \
                const int c_ = sch + p_ * 4;                                 \
                const uint32_t so_ = (uint32_t)((srow * 128 + c_ * 16)       \
                                                ^ ((srow & 7) << 4));        \
                cp_async16(smb + (SL) * 16384 + so_,                         \
                           &g_feats[(m0 + srow) * HW + kb_ + c_ * 8]);       \
                cp_async16(smb + (SL) * 16384 + 8192 + so_,                  \
                           &g_feats[(n0 + srow) * HW + kb_ + c_ * 8]);       \
            }                                                                \
            cp_commit();                                                     \
        } while (0)

        GLOAD(0, 0);
        for (int ks = 0; ks < 16; ks++) {
            const int buf = ks & 1;
            if (ks < 15) {
                GLOAD(ks + 1, buf ^ 1);
                cp_wait<1>();
            } else {
                cp_wait<0>();
            }
            __syncthreads();

            #pragma unroll
            for (int k16 = 0; k16 < 4; k16++) {
                uint32_t afr[2][4], bfr[4];
                #pragma unroll
                for (int mt = 0; mt < 2; mt++) {
                    const int ra = wm + mt * 16 + lrow;
                    const uint32_t off = (uint32_t)((ra * 128 + k16 * 32 + lkh2)
                                                    ^ ((ra & 7) << 4));
                    ldm_x4(afr[mt], smb + buf * 16384 + off);
                }
                {
                    const int rb = wn + lrow;
                    const uint32_t off = (uint32_t)((rb * 128 + k16 * 32 + lkh2)
                                                    ^ ((rb & 7) << 4));
                    ldm_x4(bfr, smb + buf * 16384 + 8192 + off);
                }
                #pragma unroll
                for (int mt = 0; mt < 2; mt++) {
                    mma_bf16(acc[mt][0], afr[mt], bfr[0], bfr[2]);
                    mma_bf16(acc[mt][1], afr[mt], bfr[1], bfr[3]);
                }
            }
            __syncthreads();
        }
        #undef GLOAD

        const float s = 1.0f / 1048576.0f;
        const int g2 = l >> 2, cc = (l & 3) * 2;
        const bool mirror = (bi != bj);
        #pragma unroll
        for (int mt = 0; mt < 2; mt++)
          #pragma unroll
          for (int h = 0; h < 2; h++) {
            const int row = m0 + wm + mt * 16 + g2;
            const int col = n0 + wn + h * 8 + cc;
            const float v0 = acc[mt][h][0] * s;
            const float v1 = acc[mt][h][1] * s;
            const float v2 = acc[mt][h][2] * s;
            const float v3 = acc[mt][h][3] * s;
            atomicAdd(&g_G[row * CH + col],           v0);
            atomicAdd(&g_G[row * CH + col + 1],       v1);
            atomicAdd(&g_G[(row + 8) * CH + col],     v2);
            atomicAdd(&g_G[(row + 8) * CH + col + 1], v3);
            if (mirror) {
                atomicAdd(&g_G[col * CH + row],           v0);
                atomicAdd(&g_G[(col + 1) * CH + row],     v1);
                atomicAdd(&g_G[col * CH + row + 8],       v2);
                atomicAdd(&g_G[(col + 1) * CH + row + 8], v3);
            }
          }

        __threadfence();
        __syncthreads();
        if (t == 0) atomicAdd(&g_gdone, 1u);      // release prefetchers
    } else {
        // ====== Lean L2 prefetch of target (linear, own stripe) ======
        const float4* tg4 = reinterpret_cast<const float4*>(target);
        float dummy = 0.f;
        int idx = (bid - NGEMM) * 256 + t;        // stride NPF*256 per load
        #pragma unroll 1
        for (int it = 0; it < 16; it++) {
            #pragma unroll
            for (int u = 0; u < 4; u++) {
                if (idx < 8388608) {
                    float4 v = __ldg(&tg4[idx]);
                    dummy += v.x + v.y + v.z + v.w;
                }
                idx += NPF * 256;
            }
            if ((it & 1) == 1) {
                unsigned g = 0;
                if (l == 0) g = ld_acq(&g_gdone);
                g = __shfl_sync(0xFFFFFFFFu, g, 0);
                if (g >= gd_tgt) break;
            }
        }
        asm volatile("" :: "f"(dummy));           // keep the loads
    }

    // ============ full barrier: G complete ============
    __threadfence();
    __syncthreads();
    if (t == 0) {
        unsigned old = atomicAdd(&g_barB, 1u);
        unsigned tgt = old - (old % NCTA) + NCTA;
        spin_to(&g_barB, tgt);
    }
    __syncthreads();

    // ====== Linear-scan loss: unit = 16 consecutive target rows ======
    // element (i,j,k): d = G[(i+j)&511][(i+k)&511] - T[i,j,k]
    const unsigned wb = ld_acq(&g_wbase);
    float accum = 0.f;

    while (true) {
        if (t == 0) *tkp = (int)(atomicAdd(&g_work, 1u) - wb);
        __syncthreads();
        const int tk = *tkp;
        __syncthreads();
        if (tk >= NUNITS) break;

        const int row0 = tk << 4;                 // 16 rows, same i-block
        const int i    = row0 >> 8;
        const int col  = (i + t) & 511;
        const int gr0  = (i + (row0 & 255)) & 511;
        const float* trow = target + (row0 << 8) + t;   // linear, +256 per row
        const float* gcol = g_G + col;                  // +512 per G row

        #pragma unroll
        for (int half = 0; half < 2; half++) {
            float tv[8], gv[8];
            #pragma unroll
            for (int u = 0; u < 8; u++) {
                const int s = half * 8 + u;
                tv[u] = __ldg(trow + (s << 8));
                gv[u] = __ldg(gcol + (((gr0 + s) & 511) << 9));
            }
            #pragma unroll
            for (int u = 0; u < 8; u++) {
                const float d = gv[u] - tv[u];
                accum = fmaf(d, d, accum);
            }
        }
    }

    // final reduce + single atomic per CTA
    #pragma unroll
    for (int o = 16; o > 0; o >>= 1)
        accum += __shfl_xor_sync(0xFFFFFFFFu, accum, o);
    if (l == 0) red[w] = accum;
    __syncthreads();
    if (t == 0) {
        float z = 0.f;
        #pragma unroll
        for (int ww = 0; ww < 8; ww++) z += red[ww];
        atomicAdd(out, z * SCALE);
    }
}

// ---------------------------------------------------------------------------
extern "C" void kernel_launch(void* const* d_in, const int* in_sizes, int n_in,
                              void* d_out, int out_size) {
    const float* x      = (const float*)d_in[0];   // (1,512,64,64) fp32
    const float* target = (const float*)d_in[1];   // (512,256,256) fp32
    float* out = (float*)d_out;

    k_all<<<NCTA, 256>>>(x, target, out);
}

// round 16
// speedup vs baseline: 1.4180x; 1.3023x over previous
#include <cuda_runtime.h>
#include <cuda_bf16.h>
#include <cstdint>

#define CH    512
#define HW    4096
#define SCALE (1.0e6f / 33554432.0f)
#define NGEMM 72
#define NS    512
#define NCTA  (NGEMM + NS)

__device__ __align__(16) __nv_bfloat16 g_feats[CH * HW];  // 4 MB bf16 feats
__device__ __align__(16) float g_G[CH * CH];              // gram (scaled 1/2^20)
__device__ unsigned int g_barA;   // convert barrier (monotonic, +NCTA per launch)
__device__ unsigned int g_barB;   // full barrier    (monotonic, +NCTA per launch)

// ---------------------------------------------------------------------------
__device__ __forceinline__ uint32_t smem_u32(const void* p) {
    return static_cast<uint32_t>(__cvta_generic_to_shared(p));
}
__device__ __forceinline__ void cp_async16(uint32_t dst, const void* src) {
    asm volatile("cp.async.cg.shared.global [%0], [%1], 16;\n" :: "r"(dst), "l"(src));
}
template <int N>
__device__ __forceinline__ void cp_wait() {
    asm volatile("cp.async.wait_group %0;\n" :: "n"(N) : "memory");
}
__device__ __forceinline__ void cp_commit() {
    asm volatile("cp.async.commit_group;\n" ::: "memory");
}
__device__ __forceinline__ void ldm_x4(uint32_t* d, uint32_t addr) {
    asm volatile("ldmatrix.sync.aligned.m8n8.x4.shared.b16 {%0,%1,%2,%3}, [%4];"
                 : "=r"(d[0]), "=r"(d[1]), "=r"(d[2]), "=r"(d[3]) : "r"(addr));
}
__device__ __forceinline__ void mma_bf16(float* c, const uint32_t* a, uint32_t b0, uint32_t b1) {
    asm volatile("mma.sync.aligned.m16n8k16.row.col.f32.bf16.bf16.f32 "
                 "{%0,%1,%2,%3},{%4,%5,%6,%7},{%8,%9},{%0,%1,%2,%3};"
                 : "+f"(c[0]), "+f"(c[1]), "+f"(c[2]), "+f"(c[3])
                 : "r"(a[0]), "r"(a[1]), "r"(a[2]), "r"(a[3]), "r"(b0), "r"(b1));
}
__device__ __forceinline__ void spin_to(unsigned int* ctr, unsigned tgt) {
    unsigned cur;
    do {
        __nanosleep(64);
        asm volatile("ld.acquire.gpu.u32 %0, [%1];" : "=r"(cur) : "l"(ctr));
    } while (cur < tgt);
}

// smem 41024B: GEMM A[2][64][144B]@0, B[2][64][144B]@18432 (36864 total)
//              S ring: 5 slots x 8KB @0 (40960); red[] reuse @0 post-loop
__global__ void __launch_bounds__(256, 4) k_all(const float* __restrict__ x,
                                                const float* __restrict__ target,
                                                float* __restrict__ out) {
    __shared__ __align__(16) char sm[41024];
    const int t = threadIdx.x;
    const int w = t >> 5, l = t & 31;
    const int bid = blockIdx.x;

    // ============ Phase 1: convert x -> bf16 (all CTAs), zero G ============
    const int gi = bid * 256 + t;                  // 0..149503
    for (int idx = gi; idx < 524288; idx += NCTA * 256) {
        float4 v = reinterpret_cast<const float4*>(x)[idx];
        __nv_bfloat162 p0, p1;
        p0.x = __float2bfloat16(v.x); p0.y = __float2bfloat16(v.y);
        p1.x = __float2bfloat16(v.z); p1.y = __float2bfloat16(v.w);
        uint2 pk;
        pk.x = *reinterpret_cast<uint32_t*>(&p0);
        pk.y = *reinterpret_cast<uint32_t*>(&p1);
        reinterpret_cast<uint2*>(g_feats)[idx] = pk;
    }
    if (gi < 65536)
        reinterpret_cast<float4*>(g_G)[gi] = make_float4(0.f, 0.f, 0.f, 0.f);
    if (gi == 0) out[0] = 0.0f;

    __threadfence();
    __syncthreads();
    if (t == 0) {
        unsigned old = atomicAdd(&g_barA, 1u);
        if (bid < NGEMM) {                  // only GEMM CTAs wait for convert
            unsigned tgt = old - (old % NCTA) + NCTA;
            spin_to(&g_barA, tgt);
        }
    }

    if (bid < NGEMM) {
        // ====== GEMM: upper-tri 64x64 tiles, splitK 2 (R7-proven, verbatim) ======
        __syncthreads();
        const int tile = bid % 36;
        const int kz   = (bid / 36) * 2048;
        int rem = tile, bi = 0;
        while (rem >= 8 - bi) { rem -= 8 - bi; bi++; }
        const int bj = bi + rem;
        const int m0 = bi * 64, n0 = bj * 64;

        const int wm = (w >> 2) * 32;
        const int wn = (w & 3) * 16;

        float acc[2][2][4];
        #pragma unroll
        for (int a = 0; a < 2; a++)
          #pragma unroll
          for (int h = 0; h < 2; h++)
            #pragma unroll
            for (int q = 0; q < 4; q++) acc[a][h][q] = 0.f;

        const int lr = t >> 3;
        const int lc = (t & 7) * 8;
        const int lrow = l & 15;
        const int lkh  = (l >> 4) * 8;
        const uint32_t smA = smem_u32(sm);
        const uint32_t smB = smA + 18432;

        auto load_stage = [&](int ks, int buf) {
            const int kb = kz + ks * 64;
            #pragma unroll
            for (int p = 0; p < 2; p++) {
                const int row = lr + p * 32;
                cp_async16(smA + buf * 9216 + row * 144 + lc * 2,
                           &g_feats[(m0 + row) * HW + kb + lc]);
                cp_async16(smB + buf * 9216 + row * 144 + lc * 2,
                           &g_feats[(n0 + row) * HW + kb + lc]);
            }
            cp_commit();
        };

        load_stage(0, 0);
        for (int ks = 0; ks < 32; ks++) {
            const int buf = ks & 1;
            if (ks < 31) {
                load_stage(ks + 1, buf ^ 1);
                cp_wait<1>();
            } else {
                cp_wait<0>();
            }
            __syncthreads();

            #pragma unroll
            for (int k16 = 0; k16 < 4; k16++) {
                uint32_t afr[2][4], bfr[4];
                #pragma unroll
                for (int mt = 0; mt < 2; mt++)
                    ldm_x4(afr[mt], smA + buf * 9216 + (wm + mt * 16 + lrow) * 144
                                        + (k16 * 16 + lkh) * 2);
                ldm_x4(bfr, smB + buf * 9216 + (wn + lrow) * 144
                                + (k16 * 16 + lkh) * 2);
                #pragma unroll
                for (int mt = 0; mt < 2; mt++) {
                    mma_bf16(acc[mt][0], afr[mt], bfr[0], bfr[2]);
                    mma_bf16(acc[mt][1], afr[mt], bfr[1], bfr[3]);
                }
            }
            __syncthreads();
        }

        const float s = 1.0f / 1048576.0f;
        const int g2 = l >> 2, cc = (l & 3) * 2;
        const bool mirror = (bi != bj);
        #pragma unroll
        for (int mt = 0; mt < 2; mt++)
          #pragma unroll
          for (int h = 0; h < 2; h++) {
            const int row = m0 + wm + mt * 16 + g2;
            const int col = n0 + wn + h * 8 + cc;
            const float v0 = acc[mt][h][0] * s;
            const float v1 = acc[mt][h][1] * s;
            const float v2 = acc[mt][h][2] * s;
            const float v3 = acc[mt][h][3] * s;
            atomicAdd(&g_G[row * CH + col],           v0);
            atomicAdd(&g_G[row * CH + col + 1],       v1);
            atomicAdd(&g_G[(row + 8) * CH + col],     v2);
            atomicAdd(&g_G[(row + 8) * CH + col + 1], v3);
            if (mirror) {
                atomicAdd(&g_G[col * CH + row],           v0);
                atomicAdd(&g_G[(col + 1) * CH + row],     v1);
                atomicAdd(&g_G[col * CH + row + 8],       v2);
                atomicAdd(&g_G[(col + 1) * CH + row + 8], v3);
            }
          }

        __threadfence();
        __syncthreads();
        if (t == 0) atomicAdd(&g_barB, 1u);      // arrive, no spin, done
        return;
    }

    // ====== S-stream: 5-slot cp.async ring, 2 stages consumed per sync ======
    const int r    = bid - NGEMM;            // 0..511
    const int base = (t - r) & 511;
    const uint32_t stg_u = smem_u32(sm);
    const float* stg = reinterpret_cast<const float*>(sm);

    float Slo = 0.f, Shi = 0.f, T2a = 0.f, T2b = 0.f;

    // stage S covers rows j = S*8 .. S*8+7; warp w loads row S*8+w
    #define ISSUE(S) do {                                                    \
        const int j_ = (S) * 8 + w;                                          \
        const int i_ = (r - j_) & 511;                                       \
        const float* src_ = target + (i_ << 16) + (j_ << 8) + l * 8;         \
        const uint32_t dst_ = stg_u + ((S) % 5) * 8192 + w * 1024 + l * 32;  \
        cp_async16(dst_, src_);                                              \
        cp_async16(dst_ + 16, src_ + 4);                                     \
        cp_commit();                                                         \
    } while (0)

    #define CONSUME(S) do {                                                  \
        const float* buf_ = stg + ((S) % 5) * 2048;                          \
        int kk_ = (base + (S) * 8) & 511;                                    \
        _Pragma("unroll")                                                    \
        for (int xx = 0; xx < 8; xx++) {                                     \
            const float v_ = buf_[xx * 256 + (kk_ & 255)];                   \
            if (xx & 1) T2b = fmaf(v_, v_, T2b);                             \
            else        T2a = fmaf(v_, v_, T2a);                             \
            if (kk_ >> 8) Shi += v_; else Slo += v_;                         \
            kk_ = (kk_ + 1) & 511;                                           \
        }                                                                    \
    } while (0)

    ISSUE(0); ISSUE(1); ISSUE(2);
    #pragma unroll 1
    for (int it = 0; it < 16; it++) {
        const int s0 = 2 * it;
        // issue ahead (stages 2it+3, 2it+4), guarded at tail
        if (s0 + 3 < 32) ISSUE(s0 + 3);
        if (s0 + 4 < 32) ISSUE(s0 + 4);
        // wait until stages s0, s0+1 have landed
        if (it <= 13)      cp_wait<3>();
        else if (it == 14) cp_wait<2>();
        else               cp_wait<0>();
        __syncthreads();
        CONSUME(s0);
        CONSUME(s0 + 1);
    }
    #undef ISSUE
    #undef CONSUME

    // ====== full barrier, then in-place combine vs G row r ======
    __syncthreads();
    if (t == 0) {
        unsigned old = atomicAdd(&g_barB, 1u);
        unsigned tgt = old - (old % NCTA) + NCTA;
        spin_to(&g_barB, tgt);
    }
    __syncthreads();

    const float Gl = g_G[r * CH + t];
    const float Gh = g_G[r * CH + t + 256];
    const int d1 = (r - t) & 511;
    const int d2 = (r - t - 256) & 511;
    const float m1 = (float)((d1 <= 256) ? 256 - d1 : d1 - 256);
    const float m2 = (float)((d2 <= 256) ? 256 - d2 : d2 - 256);
    float term = fmaf(m1 * Gl, Gl, -2.0f * Gl * Slo)
               + fmaf(m2 * Gh, Gh, -2.0f * Gh * Shi)
               + T2a + T2b;

    #pragma unroll
    for (int o = 16; o > 0; o >>= 1)
        term += __shfl_xor_sync(0xFFFFFFFFu, term, o);
    float* red = reinterpret_cast<float*>(sm);
    if (l == 0) red[w] = term;
    __syncthreads();
    if (t == 0) {
        float z = 0.f;
        #pragma unroll
        for (int ww = 0; ww < 8; ww++) z += red[ww];
        atomicAdd(out, z * SCALE);
    }
}

// ---------------------------------------------------------------------------
extern "C" void kernel_launch(void* const* d_in, const int* in_sizes, int n_in,
                              void* d_out, int out_size) {
    const float* x      = (const float*)d_in[0];   // (1,512,64,64) fp32
    const float* target = (const float*)d_in[1];   // (512,256,256) fp32
    float* out = (float*)d_out;

    k_all<<<NCTA, 256>>>(x, target, out);
}